// round 15
// baseline (speedup 1.0000x reference)
#include <cuda_runtime.h>

#define HID   1024
#define SEQ   4096
#define NRNN  32                  // RNN CTAs (persistent, wave-1 resident)
#define NGEMM 128                 // GEMM producer CTAs (exit after 8 tiles)

typedef unsigned long long u64;

// Scratch (device globals; no allocation)
__device__ float    g_emb[(size_t)SEQ * HID];   // normalized embeddings
__device__ float    g_pre[(size_t)SEQ * HID];   // W_hi @ x_t + b
__device__ unsigned g_pf[16 * 64];              // GEMM tile flags [nb][mb]
// Parity double-buffered per-consumer staging: pair = epoch<<32 | f32bits.
// Epoch e lives in slot e&1. 8B stores are single-copy atomic -> no fences.
__device__ u64      g_stage[2][NRNN][HID] __attribute__((aligned(128)));

// ---------------------------------------------------------------------------
// Kernel 0: slot 0 of every consumer := {epoch=0, h0}  (each replay)
// ---------------------------------------------------------------------------
__global__ void init_kernel(const float* __restrict__ h0) {
    int c   = blockIdx.x;            // consumer 0..31
    int tid = threadIdx.x;           // 256 threads, 4 pairs each
    #pragma unroll
    for (int j = 0; j < 4; j++) {
        int r = tid * 4 + j;
        g_stage[0][c][r] = (u64)__float_as_uint(h0[r]);   // epoch 0 high word
    }
}

// ---------------------------------------------------------------------------
// Kernel A: embedding lookup + L2 normalize; reset tile flags; out[0]=h0
// ---------------------------------------------------------------------------
__global__ void embed_kernel(const int* __restrict__ src,
                             const float* __restrict__ W,
                             const float* __restrict__ h0,
                             float* __restrict__ out) {
    int t   = blockIdx.x;
    int tid = threadIdx.x;

    if (t == 0 && tid < 256) {                         // reset tile flags
        #pragma unroll
        for (int i = 0; i < 4; i++) g_pf[tid * 4 + i] = 0u;
    }

    const float4* row = (const float4*)(W + (size_t)src[t] * HID);
    float4 v = row[tid];                       // 256 * 4 = 1024 elements
    float  ss = v.x*v.x + v.y*v.y + v.z*v.z + v.w*v.w;

    #pragma unroll
    for (int o = 16; o > 0; o >>= 1)
        ss += __shfl_xor_sync(0xffffffffu, ss, o);

    __shared__ float warp_ss[8];
    __shared__ float s_scale;
    int w = tid >> 5, l = tid & 31;
    if (l == 0) warp_ss[w] = ss;
    __syncthreads();
    if (tid == 0) {
        float tot = 0.f;
        #pragma unroll
        for (int i = 0; i < 8; i++) tot += warp_ss[i];
        float n = fmaxf(sqrtf(tot), 1e-12f);
        s_scale = 1.0f / n;
    }
    __syncthreads();

    float sc = s_scale;
    float4 o4 = make_float4(v.x*sc, v.y*sc, v.z*sc, v.w*sc);
    ((float4*)g_emb)[(size_t)t * (HID/4) + tid] = o4;

    if (t == 0)   // out row 0 = h0
        ((float4*)out)[tid] = ((const float4*)h0)[tid];
}

// ---------------------------------------------------------------------------
// Fused persistent kernel, 160 CTAs x 256 thr.
//   CTAs 32..159: GEMM producers (R13-proven, bias included), 8 tiles each.
//   CTAs 0..31: persistent RNN, push-model sync with parity staging:
//     - consumer: thread tid polls its OWN CTA's slot s&1 pairs (rows tid*4..+3)
//       until epoch == s; writes them to smem; one __syncthreads; dot.
//     - producer: after tanh, broadcast 4 values in-warp; lane l pushes pairs
//       {epoch=s+1, h} to consumer l's slot (s+1)&1  (4x st.cg.u64).
//     Deadlock-free: overwriting slot s&1 (s -> s+2) requires every CTA to
//     have finished step s, i.e. every thread already read its epoch-s pairs.
// ---------------------------------------------------------------------------
#define TK   16
#define SPAD 68

__global__ __launch_bounds__(256) void fused_kernel(const float* __restrict__ Whh,
                                                    const float* __restrict__ Whi,
                                                    const float* __restrict__ b,
                                                    float* __restrict__ out) {
    __shared__ float As[TK][SPAD];
    __shared__ float Bs[TK][SPAD];

    int tid  = threadIdx.x;
    int cta  = blockIdx.x;

    if (cta >= NRNN) {
        // ===================== GEMM producer CTAs =====================
        int gcta = cta - NRNN;
        int tx  = tid & 15;
        int ty  = tid >> 4;
        int lr  = tid >> 2;
        int lk  = (tid & 3) * 4;
        int nb  = gcta >> 3;
        int n0  = nb * 64;

        for (int j = 0; j < 8; j++) {
            int mb = (gcta & 7) * 8 + j;
            int m0 = mb * 64;

            float acc[4][4] = {};
            for (int k0 = 0; k0 < HID; k0 += TK) {
                float4 av = *(const float4*)(g_emb + (size_t)(m0 + lr) * HID + k0 + lk);
                float4 bv = *(const float4*)(Whi   + (size_t)(n0 + lr) * HID + k0 + lk);
                As[lk+0][lr] = av.x; As[lk+1][lr] = av.y; As[lk+2][lr] = av.z; As[lk+3][lr] = av.w;
                Bs[lk+0][lr] = bv.x; Bs[lk+1][lr] = bv.y; Bs[lk+2][lr] = bv.z; Bs[lk+3][lr] = bv.w;
                __syncthreads();

                #pragma unroll
                for (int kk = 0; kk < TK; kk++) {
                    float4 ra = *(const float4*)&As[kk][ty * 4];
                    float4 rb = *(const float4*)&Bs[kk][tx * 4];
                    float a[4] = {ra.x, ra.y, ra.z, ra.w};
                    float c[4] = {rb.x, rb.y, rb.z, rb.w};
                    #pragma unroll
                    for (int i = 0; i < 4; i++)
                        #pragma unroll
                        for (int jj = 0; jj < 4; jj++)
                            acc[i][jj] += a[i] * c[jj];
                }
                __syncthreads();
            }

            #pragma unroll
            for (int jj = 0; jj < 4; jj++) {
                int n = n0 + tx * 4 + jj;
                float bj = b[n];
                #pragma unroll
                for (int i = 0; i < 4; i++) {
                    int m = m0 + ty * 4 + i;
                    float v = acc[i][jj] + bj;
                    asm volatile("st.global.cg.f32 [%0], %1;"
                                 :: "l"(g_pre + (size_t)m * HID + n), "f"(v) : "memory");
                }
            }
            __syncthreads();                    // all tile stores issued CTA-wide
            if (tid == 0)
                asm volatile("st.release.gpu.global.u32 [%0], %1;"
                             :: "l"(g_pf + nb * 64 + mb), "r"(1u) : "memory");
        }
        return;
    }

    // ========================= RNN CTAs (0..31) =========================
    __shared__ float hs[HID];
    int w    = tid >> 5;
    int lane = tid & 31;
    int base = cta * 32 + w * 4;    // 4 contiguous rows per warp
    int nbc  = cta >> 1;            // 64-col n-block holding this CTA's rows

    // 4 W_hh rows per warp in registers (col = k*32 + lane)
    float wreg[4][32];
    #pragma unroll
    for (int i = 0; i < 4; i++)
        #pragma unroll
        for (int k = 0; k < 32; k++)
            wreg[i][k] = Whh[(size_t)(base + i) * HID + k * 32 + lane];

    for (int s = 0; s < SEQ; s++) {
        // ---- gate on pre-tile readiness (once per 64 steps) ----
        if ((s & 63) == 0) {
            const unsigned* fp = g_pf + nbc * 64 + (s >> 6);
            unsigned f;
            do {
                asm volatile("ld.acquire.gpu.global.u32 %0, [%1];"
                             : "=r"(f) : "l"(fp) : "memory");
            } while (!f);
        }

        // lanes 0-3: own pre value (one transaction per warp)
        float prev = 0.f;
        if (lane < 4)
            prev = __ldcg(g_pre + (size_t)s * HID + base + lane);

        // ---- wait for h_s: poll own 4 epoch-tagged pairs in slot s&1 ----
        const u64* mypairs = &g_stage[s & 1][cta][tid * 4];
        unsigned es = (unsigned)s;
        u64 x0, x1, x2, x3;
        do {
            asm volatile("ld.volatile.global.u64 %0, [%1];" : "=l"(x0) : "l"(mypairs + 0) : "memory");
            asm volatile("ld.volatile.global.u64 %0, [%1];" : "=l"(x1) : "l"(mypairs + 1) : "memory");
            asm volatile("ld.volatile.global.u64 %0, [%1];" : "=l"(x2) : "l"(mypairs + 2) : "memory");
            asm volatile("ld.volatile.global.u64 %0, [%1];" : "=l"(x3) : "l"(mypairs + 3) : "memory");
        } while ((unsigned)(x0 >> 32) != es || (unsigned)(x1 >> 32) != es ||
                 (unsigned)(x2 >> 32) != es || (unsigned)(x3 >> 32) != es);

        ((float4*)hs)[tid] = make_float4(__uint_as_float((unsigned)x0),
                                         __uint_as_float((unsigned)x1),
                                         __uint_as_float((unsigned)x2),
                                         __uint_as_float((unsigned)x3));
        __syncthreads();   // hs complete (only bar in the loop)

        // ---- 4 dots per warp ----
        float a0 = 0.f, a1 = 0.f, a2 = 0.f, a3 = 0.f;
        #pragma unroll
        for (int k = 0; k < 32; k++) {
            float h = hs[k * 32 + lane];
            a0 += wreg[0][k] * h;
            a1 += wreg[1][k] * h;
            a2 += wreg[2][k] * h;
            a3 += wreg[3][k] * h;
        }

        // ---- interleaved reduce: 6 shfls, results land on lanes 0-3 ----
        bool o1 = lane & 1, o2 = lane & 2;
        float x = o1 ? a1 : a0, y = o1 ? a0 : a1;
        x += __shfl_xor_sync(0xffffffffu, y, 1);
        float z = o1 ? a3 : a2, u = o1 ? a2 : a3;
        z += __shfl_xor_sync(0xffffffffu, u, 1);
        float p = o2 ? z : x, q = o2 ? x : z;
        p += __shfl_xor_sync(0xffffffffu, q, 2);
        p += __shfl_xor_sync(0xffffffffu, p, 4);
        p += __shfl_xor_sync(0xffffffffu, p, 8);
        p += __shfl_xor_sync(0xffffffffu, p, 16);
        // lane l (0-3) holds full dot for row base+l

        float hn = 0.f;
        if (lane < 4) {
            hn = tanhf(p + prev);
            __stcg(&out[(size_t)(s + 1) * HID + base + lane], hn);   // result
        }

        // ---- broadcast 4 new h values; push to all 32 consumers, slot (s+1)&1 ----
        float v0 = __shfl_sync(0xffffffffu, hn, 0);
        float v1 = __shfl_sync(0xffffffffu, hn, 1);
        float v2 = __shfl_sync(0xffffffffu, hn, 2);
        float v3 = __shfl_sync(0xffffffffu, hn, 3);
        u64 ehi = (u64)(unsigned)(s + 1) << 32;
        u64 p0 = ehi | __float_as_uint(v0);
        u64 p1 = ehi | __float_as_uint(v1);
        u64 p2 = ehi | __float_as_uint(v2);
        u64 p3 = ehi | __float_as_uint(v3);
        u64* dst = &g_stage[(s + 1) & 1][lane][base];   // consumer 'lane'
        asm volatile("st.global.cg.u64 [%0], %1;" :: "l"(dst + 0), "l"(p0) : "memory");
        asm volatile("st.global.cg.u64 [%0], %1;" :: "l"(dst + 1), "l"(p1) : "memory");
        asm volatile("st.global.cg.u64 [%0], %1;" :: "l"(dst + 2), "l"(p2) : "memory");
        asm volatile("st.global.cg.u64 [%0], %1;" :: "l"(dst + 3), "l"(p3) : "memory");
        // no trailing bar: next-step poll + parity staging subsume ordering
    }
}

// ---------------------------------------------------------------------------
extern "C" void kernel_launch(void* const* d_in, const int* in_sizes, int n_in,
                              void* d_out, int out_size) {
    const int*   src = (const int*)  d_in[0];
    const float* W   = (const float*)d_in[1];
    const float* h0  = (const float*)d_in[2];
    const float* Whi = (const float*)d_in[3];
    const float* Whh = (const float*)d_in[4];
    const float* b   = (const float*)d_in[5];
    float* out = (float*)d_out;

    init_kernel<<<NRNN, 256>>>(h0);
    embed_kernel<<<SEQ, 256>>>(src, W, h0, out);
    fused_kernel<<<NRNN + NGEMM, 256>>>(Whh, Whi, b, out);
}

// round 16
// speedup vs baseline: 2.5759x; 2.5759x over previous
#include <cuda_runtime.h>

#define HID   1024
#define SEQ   4096
#define NRNN  32                  // RNN CTAs (persistent, wave-1 resident)
#define NGEMM 128                 // GEMM producer CTAs (exit after 8 tiles)

// Scratch (device globals; no allocation)
__device__ float    g_emb[(size_t)SEQ * HID];   // normalized embeddings
__device__ float    g_pre[(size_t)SEQ * HID];   // W_hi @ x_t + b
__device__ unsigned g_cnt[SEQ];                 // per-step barrier counters
__device__ unsigned g_pf[16 * 64];              // GEMM tile flags [nb][mb]

// ---------------------------------------------------------------------------
// Kernel A: embedding lookup + L2 normalize; reset counters/flags; out[0]=h0
// ---------------------------------------------------------------------------
__global__ void embed_kernel(const int* __restrict__ src,
                             const float* __restrict__ W,
                             const float* __restrict__ h0,
                             float* __restrict__ out) {
    int t   = blockIdx.x;
    int tid = threadIdx.x;

    if (tid == 0) g_cnt[t] = 0u;                       // reset barrier slot
    if (t == 0 && tid < 256) {                         // reset tile flags
        #pragma unroll
        for (int i = 0; i < 4; i++) g_pf[tid * 4 + i] = 0u;
    }

    const float4* row = (const float4*)(W + (size_t)src[t] * HID);
    float4 v = row[tid];                       // 256 * 4 = 1024 elements
    float  ss = v.x*v.x + v.y*v.y + v.z*v.z + v.w*v.w;

    #pragma unroll
    for (int o = 16; o > 0; o >>= 1)
        ss += __shfl_xor_sync(0xffffffffu, ss, o);

    __shared__ float warp_ss[8];
    __shared__ float s_scale;
    int w = tid >> 5, l = tid & 31;
    if (l == 0) warp_ss[w] = ss;
    __syncthreads();
    if (tid == 0) {
        float tot = 0.f;
        #pragma unroll
        for (int i = 0; i < 8; i++) tot += warp_ss[i];
        float n = fmaxf(sqrtf(tot), 1e-12f);
        s_scale = 1.0f / n;
    }
    __syncthreads();

    float sc = s_scale;
    float4 o4 = make_float4(v.x*sc, v.y*sc, v.z*sc, v.w*sc);
    ((float4*)g_emb)[(size_t)t * (HID/4) + tid] = o4;

    if (t == 0)   // out row 0 = h0
        ((float4*)out)[tid] = ((const float4*)h0)[tid];
}

// ---------------------------------------------------------------------------
// Fused persistent kernel, 160 CTAs x 256 thr.
//   CTAs 32..159: GEMM producers (R13-proven, bias included), 8 tiles each,
//     st.release tile flag after each. Exit when done.
//   CTAs 0..31: persistent RNN with the R10-proven barrier:
//     arrive: bar C -> tid0 red.release.gpu.add g_cnt[s]
//     wait:   tid0 ld.acquire.gpu poll g_cnt[s-1] >= 32 -> bar A
//     smem staging of h (coop fill + bar B); 6-shfl reduce onto lanes 0-3;
//     parallel tanh + contiguous scalar stores.
// ---------------------------------------------------------------------------
#define TK   16
#define SPAD 68

__global__ __launch_bounds__(256) void fused_kernel(const float* __restrict__ Whh,
                                                    const float* __restrict__ Whi,
                                                    const float* __restrict__ b,
                                                    float* __restrict__ out) {
    __shared__ float As[TK][SPAD];
    __shared__ float Bs[TK][SPAD];

    int tid  = threadIdx.x;
    int cta  = blockIdx.x;

    if (cta >= NRNN) {
        // ===================== GEMM producer CTAs =====================
        int gcta = cta - NRNN;
        int tx  = tid & 15;
        int ty  = tid >> 4;
        int lr  = tid >> 2;
        int lk  = (tid & 3) * 4;
        int nb  = gcta >> 3;
        int n0  = nb * 64;

        for (int j = 0; j < 8; j++) {
            int mb = (gcta & 7) * 8 + j;
            int m0 = mb * 64;

            float acc[4][4] = {};
            for (int k0 = 0; k0 < HID; k0 += TK) {
                float4 av = *(const float4*)(g_emb + (size_t)(m0 + lr) * HID + k0 + lk);
                float4 bv = *(const float4*)(Whi   + (size_t)(n0 + lr) * HID + k0 + lk);
                As[lk+0][lr] = av.x; As[lk+1][lr] = av.y; As[lk+2][lr] = av.z; As[lk+3][lr] = av.w;
                Bs[lk+0][lr] = bv.x; Bs[lk+1][lr] = bv.y; Bs[lk+2][lr] = bv.z; Bs[lk+3][lr] = bv.w;
                __syncthreads();

                #pragma unroll
                for (int kk = 0; kk < TK; kk++) {
                    float4 ra = *(const float4*)&As[kk][ty * 4];
                    float4 rb = *(const float4*)&Bs[kk][tx * 4];
                    float a[4] = {ra.x, ra.y, ra.z, ra.w};
                    float c[4] = {rb.x, rb.y, rb.z, rb.w};
                    #pragma unroll
                    for (int i = 0; i < 4; i++)
                        #pragma unroll
                        for (int jj = 0; jj < 4; jj++)
                            acc[i][jj] += a[i] * c[jj];
                }
                __syncthreads();
            }

            #pragma unroll
            for (int jj = 0; jj < 4; jj++) {
                int n = n0 + tx * 4 + jj;
                float bj = b[n];
                #pragma unroll
                for (int i = 0; i < 4; i++) {
                    int m = m0 + ty * 4 + i;
                    float v = acc[i][jj] + bj;
                    asm volatile("st.global.cg.f32 [%0], %1;"
                                 :: "l"(g_pre + (size_t)m * HID + n), "f"(v) : "memory");
                }
            }
            __syncthreads();                    // all tile stores issued CTA-wide
            if (tid == 0)
                asm volatile("st.release.gpu.global.u32 [%0], %1;"
                             :: "l"(g_pf + nb * 64 + mb), "r"(1u) : "memory");
        }
        return;
    }

    // ========================= RNN CTAs (0..31) =========================
    __shared__ float hs[HID];
    int w    = tid >> 5;
    int lane = tid & 31;
    int base = cta * 32 + w * 4;    // 4 contiguous rows per warp
    int nbc  = cta >> 1;            // 64-col n-block holding this CTA's rows

    // 4 W_hh rows per warp in registers (col = k*32 + lane)
    float wreg[4][32];
    #pragma unroll
    for (int i = 0; i < 4; i++)
        #pragma unroll
        for (int k = 0; k < 32; k++)
            wreg[i][k] = Whh[(size_t)(base + i) * HID + k * 32 + lane];

    for (int s = 0; s < SEQ; s++) {
        // ---- gate on pre-tile readiness (once per 64 steps) ----
        if ((s & 63) == 0) {
            const unsigned* fp = g_pf + nbc * 64 + (s >> 6);
            unsigned f;
            do {
                asm volatile("ld.acquire.gpu.global.u32 %0, [%1];"
                             : "=r"(f) : "l"(fp) : "memory");
            } while (!f);
        }

        // lanes 0-3: own pre value (one transaction per warp)
        float prev = 0.f;
        if (lane < 4)
            prev = __ldcg(g_pre + (size_t)s * HID + base + lane);

        // ---- wait for h_s (single-word acquire poll, R10-proven) ----
        if (s > 0) {
            if (tid == 0) {
                unsigned v;
                do {
                    asm volatile("ld.acquire.gpu.global.u32 %0, [%1];"
                                 : "=r"(v) : "l"(g_cnt + (s - 1)) : "memory");
                } while (v < NRNN);
            }
            __syncthreads();                      // bar A: h_s globally ready
        }

        // ---- cooperative fill of h_s into smem (L2-only loads) ----
        float4 hv = __ldcg((const float4*)(out + (size_t)s * HID) + tid);
        ((float4*)hs)[tid] = hv;
        __syncthreads();                          // bar B

        // ---- 4 dots per warp ----
        float a0 = 0.f, a1 = 0.f, a2 = 0.f, a3 = 0.f;
        #pragma unroll
        for (int k = 0; k < 32; k++) {
            float h = hs[k * 32 + lane];
            a0 += wreg[0][k] * h;
            a1 += wreg[1][k] * h;
            a2 += wreg[2][k] * h;
            a3 += wreg[3][k] * h;
        }

        // ---- interleaved reduce: 6 shfls, results land on lanes 0-3 ----
        bool o1 = lane & 1, o2 = lane & 2;
        float x = o1 ? a1 : a0, y = o1 ? a0 : a1;
        x += __shfl_xor_sync(0xffffffffu, y, 1);
        float z = o1 ? a3 : a2, u = o1 ? a2 : a3;
        z += __shfl_xor_sync(0xffffffffu, u, 1);
        float p = o2 ? z : x, q = o2 ? x : z;
        p += __shfl_xor_sync(0xffffffffu, q, 2);
        p += __shfl_xor_sync(0xffffffffu, p, 4);
        p += __shfl_xor_sync(0xffffffffu, p, 8);
        p += __shfl_xor_sync(0xffffffffu, p, 16);
        // lane l (0-3) holds full dot for row base+l

        if (lane < 4) {
            float hn = tanhf(p + prev);
            __stcg(&out[(size_t)(s + 1) * HID + base + lane], hn);
        }
        __syncthreads();                          // bar C: all 32 rows stored

        if (tid == 0)   // release-arrive: orders the CTA's h stores
            asm volatile("red.release.gpu.global.add.u32 [%0], %1;"
                         :: "l"(g_cnt + s), "r"(1u) : "memory");
    }
}

// ---------------------------------------------------------------------------
extern "C" void kernel_launch(void* const* d_in, const int* in_sizes, int n_in,
                              void* d_out, int out_size) {
    const int*   src = (const int*)  d_in[0];
    const float* W   = (const float*)d_in[1];
    const float* h0  = (const float*)d_in[2];
    const float* Whi = (const float*)d_in[3];
    const float* Whh = (const float*)d_in[4];
    const float* b   = (const float*)d_in[5];
    float* out = (float*)d_out;

    embed_kernel<<<SEQ, 256>>>(src, W, h0, out);
    fused_kernel<<<NRNN + NGEMM, 256>>>(Whh, Whi, b, out);
}